// round 6
// baseline (speedup 1.0000x reference)
#include <cuda_runtime.h>
#include <cuda_bf16.h>

// AllReduce(sum over tp=8) + residual add + RMSNorm, fused single pass.
// R6: R5 (512 thr, 32-reg clamp, 4 CTAs/SM, ~100% occ) + fused dual-stream
// mainloop: both chunks accumulate in ONE TP loop so each iteration issues
// two independent LDG.128s -> deeper per-thread MLP within the same 32-reg
// budget (previously chunks ran serially, ~5 loads in flight).

constexpr int TOKENS = 4096;
constexpr int HIDDEN = 4096;
constexpr int TP     = 8;
constexpr int H4     = HIDDEN / 4;        // 1024 float4 per row
constexpr int NTHREADS = 512;
constexpr int NWARPS  = NTHREADS / 32;    // 16
constexpr float EPS = 1e-6f;

__global__ __launch_bounds__(NTHREADS, 4) void allreduce_rmsnorm_kernel(
    const float4* __restrict__ input,     // [TP, TOKENS, H4]
    const float4* __restrict__ residual,  // [TOKENS, H4]
    const float4* __restrict__ weight,    // [H4]
    float4* __restrict__ out_norm,        // [TOKENS, H4]
    float4* __restrict__ out_hidden)      // [TOKENS, H4]
{
    const int token = blockIdx.x;
    const int tid   = threadIdx.x;
    const int lane  = tid & 31;
    const int wid   = tid >> 5;

    const size_t row_off   = (size_t)token * H4;
    const size_t tp_stride = (size_t)TOKENS * H4;

    const int idx0 = tid;                 // chunk 0 element
    const int idx1 = tid + NTHREADS;      // chunk 1 element

    const float4* __restrict__ res_row = residual + row_off;
    const float4* __restrict__ in_row  = input + row_off;

    // Two independent accumulation streams, loads interleaved.
    float4 a0 = __ldcs(&res_row[idx0]);
    float4 a1 = __ldcs(&res_row[idx1]);

    #pragma unroll
    for (int t = 0; t < TP; t++) {
        const size_t base = (size_t)t * tp_stride;
        float4 v0 = __ldcs(&in_row[base + idx0]);
        float4 v1 = __ldcs(&in_row[base + idx1]);
        a0.x += v0.x; a0.y += v0.y; a0.z += v0.z; a0.w += v0.w;
        a1.x += v1.x; a1.y += v1.y; a1.z += v1.z; a1.w += v1.w;
    }

    float ss = 0.0f;
    ss = fmaf(a0.x, a0.x, ss); ss = fmaf(a0.y, a0.y, ss);
    ss = fmaf(a0.z, a0.z, ss); ss = fmaf(a0.w, a0.w, ss);
    ss = fmaf(a1.x, a1.x, ss); ss = fmaf(a1.y, a1.y, ss);
    ss = fmaf(a1.z, a1.z, ss); ss = fmaf(a1.w, a1.w, ss);

    // Residual-stream output does not depend on rstd: store before the
    // barrier so DRAM stays busy through the reduce window.
    __stcs(&out_hidden[row_off + idx0], a0);
    __stcs(&out_hidden[row_off + idx1], a1);

    // Warp reduce -> smem -> single barrier -> redundant per-thread finish.
    #pragma unroll
    for (int off = 16; off > 0; off >>= 1)
        ss += __shfl_xor_sync(0xFFFFFFFFu, ss, off);

    __shared__ float warp_ss[NWARPS];
    if (lane == 0) warp_ss[wid] = ss;
    __syncthreads();

    float tot = 0.0f;
    #pragma unroll
    for (int w = 0; w < NWARPS; w++)
        tot += warp_ss[w];
    const float rstd = rsqrtf(tot * (1.0f / (float)HIDDEN) + EPS);

    // Normalized output; weight is 16KB, reused by all CTAs -> L2-cached.
    const float4 w0 = __ldg(&weight[idx0]);
    const float4 w1 = __ldg(&weight[idx1]);
    float4 n0, n1;
    n0.x = a0.x * rstd * w0.x; n0.y = a0.y * rstd * w0.y;
    n0.z = a0.z * rstd * w0.z; n0.w = a0.w * rstd * w0.w;
    n1.x = a1.x * rstd * w1.x; n1.y = a1.y * rstd * w1.y;
    n1.z = a1.z * rstd * w1.z; n1.w = a1.w * rstd * w1.w;
    __stcs(&out_norm[row_off + idx0], n0);
    __stcs(&out_norm[row_off + idx1], n1);
}

extern "C" void kernel_launch(void* const* d_in, const int* in_sizes, int n_in,
                              void* d_out, int out_size)
{
    const float4* input    = (const float4*)d_in[0];
    const float4* residual = (const float4*)d_in[1];
    const float4* weight   = (const float4*)d_in[2];

    float4* out_norm   = (float4*)d_out;
    float4* out_hidden = (float4*)((float*)d_out + (size_t)TOKENS * HIDDEN);

    allreduce_rmsnorm_kernel<<<TOKENS, NTHREADS>>>(
        input, residual, weight, out_norm, out_hidden);
}